// round 1
// baseline (speedup 1.0000x reference)
#include <cuda_runtime.h>
#include <math.h>

#define NG 192
#define BX 32
#define BY 4
#define BZ 4
#define TX (BX + 4)      // 36
#define TY (BY + 4)      // 8
#define TZ (BZ + 4)      // 8
#define TILE (TX * TY * TZ)   // 2304
#define NTOT (NG * NG * NG)

#define KN   500000.0f
#define MU   0.5f
#define EPSF 1e-4f

__device__ __forceinline__ int wrapN(int v) {
    // v in [-2, NG+1]
    if (v < 0) v += NG;
    if (v >= NG) v -= NG;
    return v;
}

__global__ __launch_bounds__(BX * BY * BZ)
void dem_kernel(const float* __restrict__ xg, const float* __restrict__ yg,
                const float* __restrict__ zg, const float* __restrict__ vxg,
                const float* __restrict__ vyg, const float* __restrict__ vzg,
                const float* __restrict__ dptr, float* __restrict__ out,
                float eta)
{
    __shared__ float sx[TILE];
    __shared__ float sy[TILE];
    __shared__ float sz[TILE];

    const int lx = threadIdx.x, ly = threadIdx.y, lz = threadIdx.z;
    const int bx0 = blockIdx.x * BX;
    const int by0 = blockIdx.y * BY;
    const int bz0 = blockIdx.z * BZ;
    const int tid = (lz * BY + ly) * BX + lx;

    // --- cooperative halo load (wraparound) ---
    for (int idx = tid; idx < TILE; idx += BX * BY * BZ) {
        int txi = idx % TX;
        int rem = idx / TX;
        int tyi = rem % TY;
        int tzi = rem / TY;
        int gx = wrapN(bx0 + txi - 2);
        int gy = wrapN(by0 + tyi - 2);
        int gz = wrapN(bz0 + tzi - 2);
        int g = (gz * NG + gy) * NG + gx;
        sx[idx] = xg[g];
        sy[idx] = yg[g];
        sz[idx] = zg[g];
    }
    __syncthreads();

    const float d      = *dptr;
    const float two_d  = 2.0f * d;
    const float two_d2 = two_d * two_d;

    const int cz = lz + 2, cy = ly + 2, cx = lx + 2;
    const int cidx = (cz * TY + cy) * TX + cx;
    const float px = sx[cidx], py = sy[cidx], pz = sz[cidx];

    const int ga = bz0 + lz, gb = by0 + ly, gc = bx0 + lx;
    const int gidx = (ga * NG + gb) * NG + gc;

    // self velocities (cheap, coalesced)
    const float pvx = vxg[gidx], pvy = vyg[gidx], pvz = vzg[gidx];

    float fxc = 0.f, fyc = 0.f, fzc = 0.f;
    float fxd = 0.f, fyd = 0.f, fzd = 0.f;

    for (int oz = -2; oz <= 2; oz++) {
        for (int oy = -2; oy <= 2; oy++) {
            const int rowbase = ((cz + oz) * TY + (cy + oy)) * TX + cx;
            #pragma unroll
            for (int ox = -2; ox <= 2; ox++) {
                const float nx = sx[rowbase + ox];
                const float ny = sy[rowbase + ox];
                const float nz = sz[rowbase + ox];
                const float dx = px - nx;
                const float dy = py - ny;
                const float dz = pz - nz;
                const float d2 = dx * dx + dy * dy + dz * dz;
                // d2 == 0 pairs (incl. the self offset) contribute exactly 0
                // to every accumulated sum -> skip them with the same guard.
                if (d2 < two_d2 && d2 > 0.0f) {
                    const float dist = sqrtf(d2);
                    const float safe = fmaxf(EPSF, dist);
                    const float inv  = 1.0f / safe;
                    const float coef = KN * (dist - two_d) * inv;
                    fxc += coef * dx;
                    fyc += coef * dy;
                    fzc += coef * dz;
                    // neighbor velocities (rare path -> direct global)
                    const int na = wrapN(ga + oz);
                    const int nb = wrapN(gb + oy);
                    const int nc = wrapN(gc + ox);
                    const int nidx = (na * NG + nb) * NG + nc;
                    const float dvx = pvx - vxg[nidx];
                    const float dvy = pvy - vyg[nidx];
                    const float dvz = pvz - vzg[nidx];
                    const float vn  = (dvx * dx + dvy * dy + dvz * dz) * inv;
                    const float c2  = eta * vn * inv;
                    fxd += c2 * dx;
                    fyd += c2 * dy;
                    fzd += c2 * dz;
                }
            }
        }
    }

    // --- friction: only the LAST scan shift s=(2,2,2) survives, i.e.
    //     neighbor offset (-2,-2,-2), evaluated against the full sums. ---
    float frx = 0.f, fry = 0.f, frz = 0.f;
    {
        const int rb = ((cz - 2) * TY + (cy - 2)) * TX + (cx - 2);
        const float dx = px - sx[rb];
        const float dy = py - sy[rb];
        const float dz = pz - sz[rb];
        const float d2 = dx * dx + dy * dy + dz * dz;
        if (d2 < two_d2) {
            const int na = wrapN(ga - 2);
            const int nb = wrapN(gb - 2);
            const int nc = wrapN(gc - 2);
            const int nidx = (na * NG + nb) * NG + nc;
            const float dvx = pvx - vxg[nidx];
            const float dvy = pvy - vyg[nidx];
            const float dvz = pvz - vzg[nidx];
            frx = -(fabsf(fabsf(MU * fyc) + fabsf(MU * fzc) - MU * fxd)
                    * dvx / fmaxf(EPSF, fabsf(dvx)));
            fry = -(fabsf(fabsf(MU * fxc) + fabsf(MU * fzc) - MU * fyd)
                    * dvy / fmaxf(EPSF, fabsf(dvy)));
            // NB: reference uses diffvy in the z-friction numerator (kept).
            frz = -(fabsf(fabsf(MU * fxc) + fabsf(MU * fyc) - MU * fzd)
                    * dvy / fmaxf(EPSF, fabsf(dvz)));
        }
    }

    out[0 * NTOT + gidx] = fxc;
    out[1 * NTOT + gidx] = fyc;
    out[2 * NTOT + gidx] = fzc;
    out[3 * NTOT + gidx] = fxd;
    out[4 * NTOT + gidx] = fyd;
    out[5 * NTOT + gidx] = fzd;
    out[6 * NTOT + gidx] = frx;
    out[7 * NTOT + gidx] = fry;
    out[8 * NTOT + gidx] = frz;
}

extern "C" void kernel_launch(void* const* d_in, const int* in_sizes, int n_in,
                              void* d_out, int out_size)
{
    const float* xg   = (const float*)d_in[0];
    const float* yg   = (const float*)d_in[1];
    const float* zg   = (const float*)d_in[2];
    const float* vxg  = (const float*)d_in[3];
    const float* vyg  = (const float*)d_in[4];
    const float* vzg  = (const float*)d_in[5];
    const float* dptr = (const float*)d_in[6];
    float* out = (float*)d_out;

    // ETA = 2*gamma*sqrt(KN), gamma = alpha/sqrt(alpha^2+1), alpha = -ln(0.7)/pi
    const double alpha = -log(0.7) / M_PI;
    const double gam   = alpha / sqrt(alpha * alpha + 1.0);
    const float  eta   = (float)(2.0 * gam * sqrt(500000.0));

    dim3 block(BX, BY, BZ);
    dim3 grid(NG / BX, NG / BY, NG / BZ);
    dem_kernel<<<grid, block>>>(xg, yg, zg, vxg, vyg, vzg, dptr, out, eta);
}

// round 2
// speedup vs baseline: 1.4814x; 1.4814x over previous
#include <cuda_runtime.h>
#include <math.h>

#define NG 192
#define BX 32
#define BY 4
#define BZ 4
#define TX (BX + 4)      // 36
#define TY (BY + 4)      // 8
#define TZ (BZ + 4)      // 8
#define TILE (TX * TY * TZ)   // 2304
#define NTOT (NG * NG * NG)

#define KN   500000.0f
#define MU   0.5f
#define EPSF 1e-4f
#define FULLMASK 0xffffffffu

__device__ __forceinline__ int wrapN(int v) {
    if (v < 0) v += NG;
    if (v >= NG) v -= NG;
    return v;
}

__global__ __launch_bounds__(BX * BY * BZ)
void dem_kernel(const float* __restrict__ xg, const float* __restrict__ yg,
                const float* __restrict__ zg, const float* __restrict__ vxg,
                const float* __restrict__ vyg, const float* __restrict__ vzg,
                const float* __restrict__ dptr, float* __restrict__ out,
                float eta)
{
    __shared__ float2 sxy[TILE];   // packed (x,y) -> one LDS.64 in hot path
    __shared__ float  sz[TILE];

    const int lx = threadIdx.x, ly = threadIdx.y, lz = threadIdx.z;
    const int bx0 = blockIdx.x * BX;
    const int by0 = blockIdx.y * BY;
    const int bz0 = blockIdx.z * BZ;
    const int tid = (lz * BY + ly) * BX + lx;

    // --- cooperative halo load (wraparound) ---
    for (int idx = tid; idx < TILE; idx += BX * BY * BZ) {
        int txi = idx % TX;
        int rem = idx / TX;
        int tyi = rem % TY;
        int tzi = rem / TY;
        int gx = wrapN(bx0 + txi - 2);
        int gy = wrapN(by0 + tyi - 2);
        int gz = wrapN(bz0 + tzi - 2);
        int g = (gz * NG + gy) * NG + gx;
        sxy[idx] = make_float2(xg[g], yg[g]);
        sz[idx]  = zg[g];
    }
    __syncthreads();

    const float d      = *dptr;
    const float two_d  = 2.0f * d;
    const float two_d2 = two_d * two_d;

    const int cz = lz + 2, cy = ly + 2, cx = lx + 2;
    const int cidx = (cz * TY + cy) * TX + cx;
    const float2 pxy = sxy[cidx];
    const float px = pxy.x, py = pxy.y, pz = sz[cidx];

    const int ga = bz0 + lz, gb = by0 + ly, gc = bx0 + lx;
    const int gidx = (ga * NG + gb) * NG + gc;

    // self velocities (coalesced, once)
    const float pvx = vxg[gidx], pvy = vyg[gidx], pvz = vzg[gidx];

    float fxc = 0.f, fyc = 0.f, fzc = 0.f;
    float fxd = 0.f, fyd = 0.f, fzd = 0.f;

    for (int oz = -2; oz <= 2; oz++) {
        #pragma unroll
        for (int oy = -2; oy <= 2; oy++) {
            const int rowbase = ((cz + oz) * TY + (cy + oy)) * TX + cx;
            #pragma unroll
            for (int ox = -2; ox <= 2; ox++) {
                // ---- cheap prefilter: dx^2 + dy^2 already exceeds 2d^2
                //      for 99.99% of pairs; d2 >= dx^2+dy^2, so no hits lost.
                const float2 nxy = sxy[rowbase + ox];
                const float dx = px - nxy.x;
                const float dy = py - nxy.y;
                const float r2 = fmaf(dy, dy, dx * dx);
                const bool pre = r2 < two_d2;
                if (__any_sync(FULLMASK, pre)) {           // ~0.35% taken
                    const float dz = pz - sz[rowbase + ox];
                    const float d2 = fmaf(dz, dz, r2);
                    // d2 == 0 pairs (incl. self offset) contribute exactly 0.
                    const bool hit = (d2 < two_d2) && (d2 > 0.0f);
                    if (__any_sync(FULLMASK, hit)) {       // ~never taken
                        if (hit) {
                            const float dist = sqrtf(d2);
                            const float safe = fmaxf(EPSF, dist);
                            const float inv  = 1.0f / safe;
                            const float coef = KN * (dist - two_d) * inv;
                            fxc += coef * dx;
                            fyc += coef * dy;
                            fzc += coef * dz;
                            const int na = wrapN(ga + oz);
                            const int nb = wrapN(gb + oy);
                            const int nc = wrapN(gc + ox);
                            const int nidx = (na * NG + nb) * NG + nc;
                            const float dvx = pvx - vxg[nidx];
                            const float dvy = pvy - vyg[nidx];
                            const float dvz = pvz - vzg[nidx];
                            const float vn  = (dvx * dx + dvy * dy + dvz * dz) * inv;
                            const float c2  = eta * vn * inv;
                            fxd += c2 * dx;
                            fyd += c2 * dy;
                            fzd += c2 * dz;
                        }
                    }
                }
            }
        }
    }

    // --- friction: only the LAST scan shift s=(2,2,2) survives, i.e.
    //     neighbor offset (-2,-2,-2), against the fully accumulated sums. ---
    float frx = 0.f, fry = 0.f, frz = 0.f;
    {
        const int rb = ((cz - 2) * TY + (cy - 2)) * TX + (cx - 2);
        const float2 nxy = sxy[rb];
        const float dx = px - nxy.x;
        const float dy = py - nxy.y;
        const float r2 = fmaf(dy, dy, dx * dx);
        if (__any_sync(FULLMASK, r2 < two_d2)) {
            const float dz = pz - sz[rb];
            const float d2 = fmaf(dz, dz, r2);
            if (d2 < two_d2) {
                const int na = wrapN(ga - 2);
                const int nb = wrapN(gb - 2);
                const int nc = wrapN(gc - 2);
                const int nidx = (na * NG + nb) * NG + nc;
                const float dvx = pvx - vxg[nidx];
                const float dvy = pvy - vyg[nidx];
                const float dvz = pvz - vzg[nidx];
                frx = -(fabsf(fabsf(MU * fyc) + fabsf(MU * fzc) - MU * fxd)
                        * dvx / fmaxf(EPSF, fabsf(dvx)));
                fry = -(fabsf(fabsf(MU * fxc) + fabsf(MU * fzc) - MU * fyd)
                        * dvy / fmaxf(EPSF, fabsf(dvy)));
                // NB: reference uses diffvy in the z-friction numerator (kept).
                frz = -(fabsf(fabsf(MU * fxc) + fabsf(MU * fyc) - MU * fzd)
                        * dvy / fmaxf(EPSF, fabsf(dvz)));
            }
        }
    }

    out[0 * NTOT + gidx] = fxc;
    out[1 * NTOT + gidx] = fyc;
    out[2 * NTOT + gidx] = fzc;
    out[3 * NTOT + gidx] = fxd;
    out[4 * NTOT + gidx] = fyd;
    out[5 * NTOT + gidx] = fzd;
    out[6 * NTOT + gidx] = frx;
    out[7 * NTOT + gidx] = fry;
    out[8 * NTOT + gidx] = frz;
}

extern "C" void kernel_launch(void* const* d_in, const int* in_sizes, int n_in,
                              void* d_out, int out_size)
{
    const float* xg   = (const float*)d_in[0];
    const float* yg   = (const float*)d_in[1];
    const float* zg   = (const float*)d_in[2];
    const float* vxg  = (const float*)d_in[3];
    const float* vyg  = (const float*)d_in[4];
    const float* vzg  = (const float*)d_in[5];
    const float* dptr = (const float*)d_in[6];
    float* out = (float*)d_out;

    // ETA = 2*gamma*sqrt(KN), gamma = alpha/sqrt(alpha^2+1), alpha = -ln(0.7)/pi
    const double alpha = -log(0.7) / M_PI;
    const double gam   = alpha / sqrt(alpha * alpha + 1.0);
    const float  eta   = (float)(2.0 * gam * sqrt(500000.0));

    dim3 block(BX, BY, BZ);
    dim3 grid(NG / BX, NG / BY, NG / BZ);
    dem_kernel<<<grid, block>>>(xg, yg, zg, vxg, vyg, vzg, dptr, out, eta);
}